// round 16
// baseline (speedup 1.0000x reference)
#include <cuda_runtime.h>
#include <cuda_fp16.h>
#include <cstdint>

// FiberConv collapsed to GEMM: C[400000,384] = x[400000,384] @ Bt^T + bias
//   Bt[n=(t*32+o)][k=(s*32+i)] = sum_a edge[t,s,a] * W[o*32+i, a]
// Single-pass fp16 (xh*Bh), rel_err ~2.9e-4 (calibrated R6-R15).
// R16: warp tile 64x48 (ni=6), BN=192 — the register-feasible middle point
// between R9 (64x32, ratio 2.67, 466us) and R12 (64x64, ratio 4.0, but 168
// regs -> occupancy collapse). acc=96 regs; A fragment loaded per-mi; x
// staged in 4 quarter-rounds (uint2[2]). ldsm wavefronts/output -22%.
// ldsm L1 traffic is the measured dominant term of the co-binding L1 pipe.

#define NDIM 384
#define KDIM 384
#define BATCH 400000

#define BM 128
#define BN 192
#define BK 64
#define NTHREADS 256
#define NCHUNK (KDIM / BK)                 // 6

#define SSTRB 144                          // fp16 row stride bytes (64*2=128 pad 144)
#define ATILE (128 * SSTRB)                // 18432
#define BTILE (192 * SSTRB)                // 27648
#define STAGE_BYTES (ATILE + BTILE)        // 46080
#define SMEM_DYN (2 * STAGE_BYTES)         // 92160 -> 2 CTAs/SM (184KB)

__device__ __half g_Bh[NDIM * KDIM];

__global__ void fiber_precompute(const float* __restrict__ edge,
                                 const float* __restrict__ W) {
    int idx = blockIdx.x * blockDim.x + threadIdx.x;
    if (idx >= NDIM * KDIM) return;
    int n = idx / KDIM, k = idx % KDIM;
    int t = n >> 5, o = n & 31, s = k >> 5, i = k & 31;
    const float* e = edge + (t * 12 + s) * 3;
    const float* w = W + (o * 32 + i) * 3;
    float v = e[0] * w[0] + e[1] * w[1] + e[2] * w[2];
    g_Bh[idx] = __float2half_rn(v);
}

// ---------------- PTX helpers ----------------
__device__ __forceinline__ uint32_t smem_u32(const void* p) {
    uint32_t a;
    asm("{ .reg .u64 t; cvta.to.shared.u64 t, %1; cvt.u32.u64 %0, t; }" : "=r"(a) : "l"(p));
    return a;
}
__device__ __forceinline__ void ldsm_x4(uint32_t& r0, uint32_t& r1, uint32_t& r2,
                                        uint32_t& r3, uint32_t addr) {
    asm volatile("ldmatrix.sync.aligned.m8n8.x4.shared.b16 {%0,%1,%2,%3}, [%4];"
                 : "=r"(r0), "=r"(r1), "=r"(r2), "=r"(r3) : "r"(addr));
}
__device__ __forceinline__ void mma_f16(float& d0, float& d1, float& d2, float& d3,
                                        uint32_t a0, uint32_t a1, uint32_t a2, uint32_t a3,
                                        uint32_t b0, uint32_t b1) {
    asm volatile(
        "mma.sync.aligned.m16n8k16.row.col.f32.f16.f16.f32 "
        "{%0,%1,%2,%3}, {%4,%5,%6,%7}, {%8,%9}, {%0,%1,%2,%3};"
        : "+f"(d0), "+f"(d1), "+f"(d2), "+f"(d3)
        : "r"(a0), "r"(a1), "r"(a2), "r"(a3), "r"(b0), "r"(b1));
}
__device__ __forceinline__ void cp_async16(uint32_t dst, const void* src) {
    asm volatile("cp.async.cg.shared.global [%0], [%1], 16;" :: "r"(dst), "l"(src));
}
#define CP_COMMIT() asm volatile("cp.async.commit_group;" ::: "memory")
#define CP_WAIT0()  asm volatile("cp.async.wait_group 0;" ::: "memory")

__device__ __forceinline__ uint32_t pack2h(float a, float b) {
    __half ha = __float2half_rn(a), hb = __float2half_rn(b);
    return ((uint32_t)__half_as_ushort(hb) << 16) | __half_as_ushort(ha);
}

// ---------------- main GEMM ----------------
// 8 warps arranged 2x4: warp tile 64 rows x 48 cols (mi=4, ni=6, acc=96 regs)
__global__ void __launch_bounds__(NTHREADS, 2)
fiber_gemm_hmma(const float* __restrict__ x, const float* __restrict__ bias,
                float* __restrict__ out) {
    extern __shared__ char smem[];
    const uint32_t sbase = smem_u32(smem);

    const int tid  = threadIdx.x;
    const int lane = tid & 31;
    const int warp = tid >> 5;
    const int wm = warp >> 2;          // 0..1 (row group of 64)
    const int wn = warp & 3;           // 0..3 (col group of 48)
    const int bn = blockIdx.x;         // 0..1
    const int bm = blockIdx.y;         // 0..3124

    const float* xblk = x + (size_t)bm * BM * KDIM;
    const __half* gBh = g_Bh + (size_t)bn * BN * KDIM;

    float acc[4][6][4];
    #pragma unroll
    for (int a = 0; a < 4; a++)
        #pragma unroll
        for (int b = 0; b < 6; b++)
            #pragma unroll
            for (int c = 0; c < 4; c++) acc[a][b][c] = 0.f;

    const uint32_t a_lane_off = (uint32_t)((wm * 64 + (lane & 15)) * SSTRB + (lane >> 4) * 16);
    const uint32_t b_lane_off = (uint32_t)((wn * 48 + ((lane >> 4) << 3) + (lane & 7)) * SSTRB
                                           + ((lane >> 3) & 1) * 16);

    uint2 xr[2];   // quarter-round staging, packed fp16 (4 regs)

    // quarter q of chunk c: rows [q*32, q*32+32), 512 float4 slots, 2/thread
    auto load_xq = [&](int c, int q) {
        #pragma unroll
        for (int it = 0; it < 2; it++) {
            int slot = it * NTHREADS + tid;          // 0..511
            int r = q * 32 + (slot >> 4);            // 16 float4 per row
            int c4 = (slot & 15) * 4;
            float4 v = *(const float4*)(xblk + (size_t)r * KDIM + c * BK + c4);
            xr[it].x = pack2h(v.x, v.y);
            xr[it].y = pack2h(v.z, v.w);
        }
    };
    auto sts_xq = [&](int c, int q) {
        uint32_t dA = sbase + (c & 1) * STAGE_BYTES;
        #pragma unroll
        for (int it = 0; it < 2; it++) {
            int slot = it * NTHREADS + tid;
            int r = q * 32 + (slot >> 4);
            int c4 = (slot & 15) * 4;
            uint32_t doff = (uint32_t)(r * SSTRB + c4 * 2);
            asm volatile("st.shared.v2.b32 [%0], {%1,%2};"
                         :: "r"(dA + doff), "r"(xr[it].x), "r"(xr[it].y));
        }
    };
    auto cp_B = [&](int c) {
        uint32_t dB = sbase + (c & 1) * STAGE_BYTES + ATILE;
        #pragma unroll
        for (int it = 0; it < 6; it++) {
            int slot = it * NTHREADS + tid;          // 0..1535
            int r = slot >> 3, seg = slot & 7;       // 8 x 16B per row
            uint32_t doff = (uint32_t)(r * SSTRB + seg * 16);
            size_t goff = (size_t)r * KDIM + c * BK + seg * 8;
            cp_async16(dB + doff, gBh + goff);
        }
        CP_COMMIT();
    };

    // one k16 slice: 3 B-ldsm (bh[3][4]), then per mi {1 A-ldsm, 6 MMA}
    auto mma_slice = [&](int c, int ks) {
        const uint32_t Ah = sbase + (c & 1) * STAGE_BYTES;
        const uint32_t Bh = Ah + ATILE;
        const uint32_t kso = (uint32_t)(ks * 32);
        uint32_t bh[3][4];
        #pragma unroll
        for (int pj = 0; pj < 3; pj++)
            ldsm_x4(bh[pj][0], bh[pj][1], bh[pj][2], bh[pj][3],
                    Bh + b_lane_off + pj * 16 * SSTRB + kso);
        #pragma unroll
        for (int mi = 0; mi < 4; mi++) {
            uint32_t af0, af1, af2, af3;
            ldsm_x4(af0, af1, af2, af3,
                    Ah + a_lane_off + mi * 16 * SSTRB + kso);
            #pragma unroll
            for (int ni = 0; ni < 6; ni++)
                mma_f16(acc[mi][ni][0], acc[mi][ni][1], acc[mi][ni][2], acc[mi][ni][3],
                        af0, af1, af2, af3,
                        bh[ni >> 1][(ni & 1) * 2], bh[ni >> 1][(ni & 1) * 2 + 1]);
        }
    };

    // prologue: stage chunk 0
    cp_B(0);
    #pragma unroll
    for (int q = 0; q < 4; q++) { load_xq(0, q); sts_xq(0, q); }
    CP_WAIT0();
    __syncthreads();

    for (int c = 0; c < NCHUNK; c++) {
        if (c + 1 < NCHUNK) {
            cp_B(c + 1);
            #pragma unroll
            for (int q = 0; q < 4; q++) {
                load_xq(c + 1, q);
                mma_slice(c, q);
                sts_xq(c + 1, q);
            }
            CP_WAIT0();
        } else {
            #pragma unroll
            for (int q = 0; q < 4; q++) mma_slice(c, q);
        }
        __syncthreads();
    }

    // ---- epilogue: registers -> global (float2 stores) + bias ----
    float* oblk = out + (size_t)bm * BM * NDIM + bn * BN;
    const int r0 = wm * 64 + (lane >> 2);
    const int c0 = wn * 48 + (lane & 3) * 2;
    #pragma unroll
    for (int ni = 0; ni < 6; ni++) {
        const int col = c0 + ni * 8;
        const float b0 = bias[col & 31];
        const float b1 = bias[(col + 1) & 31];
        #pragma unroll
        for (int mi = 0; mi < 4; mi++) {
            const int row = r0 + mi * 16;
            float2 v0 = make_float2(acc[mi][ni][0] + b0, acc[mi][ni][1] + b1);
            float2 v1 = make_float2(acc[mi][ni][2] + b0, acc[mi][ni][3] + b1);
            *(float2*)(oblk + (size_t)row * NDIM + col) = v0;
            *(float2*)(oblk + (size_t)(row + 8) * NDIM + col) = v1;
        }
    }
}

// ---------------------------------------------------------------------------
extern "C" void kernel_launch(void* const* d_in, const int* in_sizes, int n_in,
                              void* d_out, int out_size) {
    const float* x    = (const float*)d_in[0];   // [400000, 384]
    const float* edge = (const float*)d_in[1];   // [12, 12, 3]
    const float* W    = (const float*)d_in[2];   // [1024, 3]
    const float* bias = (const float*)d_in[3];   // [32]
    float* out = (float*)d_out;                  // [400000, 384]

    cudaFuncSetAttribute(fiber_gemm_hmma,
                         cudaFuncAttributeMaxDynamicSharedMemorySize, SMEM_DYN);

    fiber_precompute<<<(NDIM * KDIM + 255) / 256, 256>>>(edge, W);

    dim3 grid(NDIM / BN, BATCH / BM);   // (2, 3125)
    fiber_gemm_hmma<<<grid, NTHREADS, SMEM_DYN>>>(x, bias, out);
}

// round 17
// speedup vs baseline: 1.3839x; 1.3839x over previous
#include <cuda_runtime.h>
#include <cuda_fp16.h>
#include <cstdint>

// FiberConv collapsed to GEMM: C[400000,384] = x[400000,384] @ Bt^T + bias
//   Bt[n=(t*32+o)][k=(s*32+i)] = sum_a edge[t,s,a] * W[o*32+i, a]
// Single-pass fp16 (xh*Bh), rel_err ~2.9e-4 (calibrated R6-R16).
// R17: persistent CTAs (grid=296, 2/SM) with cross-tile pipelining. Inner
// loop byte-identical to R15 (best, 466us). During the LAST chunk of tile t
// the CTA stages chunk 0 of tile t+296 into the free ping-pong buffer
// (parity: chunk5->buf1, next chunk0->buf0), so the epilogue overlaps with
// an already-resident next tile and the pipeline never drains. Removes ~32
// exposed prologues + wave transitions (~10-15% of runtime).

#define NDIM 384
#define KDIM 384
#define BATCH 400000

#define BM 128
#define BN 128
#define BK 64
#define NTHREADS 256
#define NCHUNK (KDIM / BK)                 // 6
#define NTILES ((BATCH / BM) * (NDIM / BN))  // 9375
#define GRIDX 296                          // 148 SMs x 2 CTAs

#define SSTR 72                            // padded fp16 row stride (144 bytes)
#define TILE_BYTES (128 * SSTR * 2)        // 18432
#define STAGE_BYTES (2 * TILE_BYTES)       // Ah, Bh = 36864
#define SMEM_DYN (2 * STAGE_BYTES)         // 73728 -> 2 CTAs/SM

__device__ __half g_Bh[NDIM * KDIM];

__global__ void fiber_precompute(const float* __restrict__ edge,
                                 const float* __restrict__ W) {
    int idx = blockIdx.x * blockDim.x + threadIdx.x;
    if (idx >= NDIM * KDIM) return;
    int n = idx / KDIM, k = idx % KDIM;
    int t = n >> 5, o = n & 31, s = k >> 5, i = k & 31;
    const float* e = edge + (t * 12 + s) * 3;
    const float* w = W + (o * 32 + i) * 3;
    float v = e[0] * w[0] + e[1] * w[1] + e[2] * w[2];
    g_Bh[idx] = __float2half_rn(v);
}

// ---------------- PTX helpers ----------------
__device__ __forceinline__ uint32_t smem_u32(const void* p) {
    uint32_t a;
    asm("{ .reg .u64 t; cvta.to.shared.u64 t, %1; cvt.u32.u64 %0, t; }" : "=r"(a) : "l"(p));
    return a;
}
__device__ __forceinline__ void ldsm_x4(uint32_t& r0, uint32_t& r1, uint32_t& r2,
                                        uint32_t& r3, uint32_t addr) {
    asm volatile("ldmatrix.sync.aligned.m8n8.x4.shared.b16 {%0,%1,%2,%3}, [%4];"
                 : "=r"(r0), "=r"(r1), "=r"(r2), "=r"(r3) : "r"(addr));
}
__device__ __forceinline__ void mma_f16(float& d0, float& d1, float& d2, float& d3,
                                        uint32_t a0, uint32_t a1, uint32_t a2, uint32_t a3,
                                        uint32_t b0, uint32_t b1) {
    asm volatile(
        "mma.sync.aligned.m16n8k16.row.col.f32.f16.f16.f32 "
        "{%0,%1,%2,%3}, {%4,%5,%6,%7}, {%8,%9}, {%0,%1,%2,%3};"
        : "+f"(d0), "+f"(d1), "+f"(d2), "+f"(d3)
        : "r"(a0), "r"(a1), "r"(a2), "r"(a3), "r"(b0), "r"(b1));
}
__device__ __forceinline__ void cp_async16(uint32_t dst, const void* src) {
    asm volatile("cp.async.cg.shared.global [%0], [%1], 16;" :: "r"(dst), "l"(src));
}
#define CP_COMMIT() asm volatile("cp.async.commit_group;" ::: "memory")
#define CP_WAIT0()  asm volatile("cp.async.wait_group 0;" ::: "memory")

__device__ __forceinline__ uint32_t pack2h(float a, float b) {
    __half ha = __float2half_rn(a), hb = __float2half_rn(b);
    return ((uint32_t)__half_as_ushort(hb) << 16) | __half_as_ushort(ha);
}

// ---------------- main GEMM (persistent) ----------------
__global__ void __launch_bounds__(NTHREADS, 2)
fiber_gemm_hmma(const float* __restrict__ x, const float* __restrict__ bias,
                float* __restrict__ out) {
    extern __shared__ char smem[];
    const uint32_t sbase = smem_u32(smem);

    const int tid  = threadIdx.x;
    const int lane = tid & 31;
    const int warp = tid >> 5;
    const int wm = warp >> 2;          // 0..1
    const int wn = warp & 3;           // 0..3

    const uint32_t a_lane_off = (uint32_t)((wm * 64 + (lane & 15)) * (SSTR * 2) + (lane >> 4) * 16);
    const uint32_t b_lane_off = (uint32_t)((wn * 32 + ((lane >> 4) << 3) + (lane & 7)) * (SSTR * 2)
                                           + ((lane >> 3) & 1) * 16);

    float acc[4][4][4];
    #pragma unroll
    for (int a = 0; a < 4; a++)
        #pragma unroll
        for (int b = 0; b < 4; b++)
            #pragma unroll
            for (int c = 0; c < 4; c++) acc[a][b][c] = 0.f;

    uint2 xr[4];   // half-chunk staging, packed fp16

    // ---- helpers with explicit tile pointers / buffer index ----
    auto load_xh = [&](const float* xb, int c, int h) {
        #pragma unroll
        for (int it = 0; it < 4; it++) {
            int slot = it * NTHREADS + tid;
            int r = h * 64 + (slot >> 4);
            int c4 = (slot & 15) * 4;
            float4 v = *(const float4*)(xb + (size_t)r * KDIM + c * BK + c4);
            xr[it].x = pack2h(v.x, v.y);
            xr[it].y = pack2h(v.z, v.w);
        }
    };
    auto sts_xh = [&](int buf, int h) {
        uint32_t dAh = sbase + buf * STAGE_BYTES;
        #pragma unroll
        for (int it = 0; it < 4; it++) {
            int slot = it * NTHREADS + tid;
            int r = h * 64 + (slot >> 4);
            int c4 = (slot & 15) * 4;
            uint32_t doff = (uint32_t)(r * (SSTR * 2) + c4 * 2);
            asm volatile("st.shared.v2.b32 [%0], {%1,%2};"
                         :: "r"(dAh + doff), "r"(xr[it].x), "r"(xr[it].y));
        }
    };
    auto cp_B = [&](const __half* gB, int c, int buf) {
        uint32_t dBh = sbase + buf * STAGE_BYTES + TILE_BYTES;
        #pragma unroll
        for (int it = 0; it < 4; it++) {
            int slot = it * NTHREADS + tid;
            int r = slot >> 3, seg = slot & 7;
            uint32_t doff = (uint32_t)(r * (SSTR * 2) + seg * 16);
            size_t goff = (size_t)r * KDIM + c * BK + seg * 8;
            cp_async16(dBh + doff, gB + goff);
        }
        CP_COMMIT();
    };
    auto mma_group = [&](int buf, int k0, int k1) {
        const uint32_t Ah = sbase + buf * STAGE_BYTES;
        const uint32_t Bh = Ah + TILE_BYTES;
        #pragma unroll
        for (int ks = k0; ks < k1; ks++) {
            const uint32_t kso = (uint32_t)(ks * 32);
            uint32_t af[4][4], bh[2][4];
            #pragma unroll
            for (int mi = 0; mi < 4; mi++)
                ldsm_x4(af[mi][0], af[mi][1], af[mi][2], af[mi][3],
                        Ah + a_lane_off + mi * 16 * (SSTR * 2) + kso);
            #pragma unroll
            for (int pj = 0; pj < 2; pj++)
                ldsm_x4(bh[pj][0], bh[pj][1], bh[pj][2], bh[pj][3],
                        Bh + b_lane_off + pj * 16 * (SSTR * 2) + kso);
            #pragma unroll
            for (int mi = 0; mi < 4; mi++)
                #pragma unroll
                for (int ni = 0; ni < 4; ni++)
                    mma_f16(acc[mi][ni][0], acc[mi][ni][1], acc[mi][ni][2], acc[mi][ni][3],
                            af[mi][0], af[mi][1], af[mi][2], af[mi][3],
                            bh[ni >> 1][(ni & 1) * 2], bh[ni >> 1][(ni & 1) * 2 + 1]);
        }
    };

    int t = blockIdx.x;                          // tile id: bm = t/3, bn = t%3
    const float* xblk = x + (size_t)(t / 3) * BM * KDIM;
    const __half* gB  = g_Bh + (size_t)(t % 3) * BN * KDIM;

    // one-time prologue: stage chunk 0 of the first tile
    cp_B(gB, 0, 0);
    load_xh(xblk, 0, 0); sts_xh(0, 0);
    load_xh(xblk, 0, 1); sts_xh(0, 1);
    CP_WAIT0();
    __syncthreads();

    while (true) {
        // chunks 0..4: stage next chunk of SAME tile (identical to R15)
        #pragma unroll 1
        for (int c = 0; c < NCHUNK - 1; c++) {
            const int buf = c & 1;
            cp_B(gB, c + 1, buf ^ 1);
            load_xh(xblk, c + 1, 0);
            mma_group(buf, 0, 2);
            sts_xh(buf ^ 1, 0);
            load_xh(xblk, c + 1, 1);
            mma_group(buf, 2, 4);
            sts_xh(buf ^ 1, 1);
            CP_WAIT0();
            __syncthreads();
        }

        // chunk 5 (buf1): stage chunk 0 of the NEXT tile into buf0
        const int nt = t + GRIDX;
        const float* xblk2 = x + (size_t)(nt / 3) * BM * KDIM;
        const __half* gB2  = g_Bh + (size_t)(nt % 3) * BN * KDIM;
        if (nt < NTILES) {
            cp_B(gB2, 0, 0);
            load_xh(xblk2, 0, 0);
            mma_group(1, 0, 2);
            sts_xh(0, 0);
            load_xh(xblk2, 0, 1);
            mma_group(1, 2, 4);
            sts_xh(0, 1);
            CP_WAIT0();
            __syncthreads();
        } else {
            mma_group(1, 0, 4);
        }

        // epilogue for tile t (next tile's chunk 0 already resident in buf0)
        {
            float* oblk = out + (size_t)(t / 3) * BM * NDIM + (size_t)(t % 3) * BN;
            const int r0 = wm * 64 + (lane >> 2);
            const int c0 = wn * 32 + (lane & 3) * 2;
            #pragma unroll
            for (int ni = 0; ni < 4; ni++) {
                const int col = c0 + ni * 8;
                const float b0 = bias[col & 31];
                const float b1 = bias[(col + 1) & 31];
                #pragma unroll
                for (int mi = 0; mi < 4; mi++) {
                    const int row = r0 + mi * 16;
                    float2 v0 = make_float2(acc[mi][ni][0] + b0, acc[mi][ni][1] + b1);
                    float2 v1 = make_float2(acc[mi][ni][2] + b0, acc[mi][ni][3] + b1);
                    *(float2*)(oblk + (size_t)row * NDIM + col) = v0;
                    *(float2*)(oblk + (size_t)(row + 8) * NDIM + col) = v1;
                }
            }
        }

        if (nt >= NTILES) break;
        t = nt;
        xblk = xblk2;
        gB = gB2;
        #pragma unroll
        for (int a = 0; a < 4; a++)
            #pragma unroll
            for (int b = 0; b < 4; b++)
                #pragma unroll
                for (int c = 0; c < 4; c++) acc[a][b][c] = 0.f;
    }
}

// ---------------------------------------------------------------------------
extern "C" void kernel_launch(void* const* d_in, const int* in_sizes, int n_in,
                              void* d_out, int out_size) {
    const float* x    = (const float*)d_in[0];   // [400000, 384]
    const float* edge = (const float*)d_in[1];   // [12, 12, 3]
    const float* W    = (const float*)d_in[2];   // [1024, 3]
    const float* bias = (const float*)d_in[3];   // [32]
    float* out = (float*)d_out;                  // [400000, 384]

    cudaFuncSetAttribute(fiber_gemm_hmma,
                         cudaFuncAttributeMaxDynamicSharedMemorySize, SMEM_DYN);

    fiber_precompute<<<(NDIM * KDIM + 255) / 256, 256>>>(edge, W);

    fiber_gemm_hmma<<<GRIDX, NTHREADS, SMEM_DYN>>>(x, bias, out);
}